// round 14
// baseline (speedup 1.0000x reference)
#include <cuda_runtime.h>
#include <cuda_bf16.h>
#include <math.h>

// Problem constants (shapes fixed by the reference setup)
#define NMAX   40000
#define EMAX   400000
#define EPRIME (EMAX + NMAX)

// ---------------- device scratch (no allocation allowed) ----------------
// bufA holds h as packed bf16 (M/2 uint32 per row). bufB holds fp32 agg output.
__device__ unsigned g_bufA[NMAX * 128];   // bf16x2: up to 256 cols
__device__ float    g_bufB[NMAX * 256];
__device__ float g_alsA[NMAX], g_aldA[NMAX];
__device__ float g_alsB[NMAX], g_aldB[NMAX];
__device__ float g_alsC[NMAX], g_aldC[NMAX];
__device__ float g_escr[EPRIME];      // fallback scratch for high-degree nodes
__device__ int   g_deg[NMAX];
__device__ int   g_rowptr[NMAX + 1];
__device__ int   g_cursor[NMAX + 1];
__device__ int   g_srcs[EPRIME];      // src node of each dst-sorted edge
__device__ int   g_is64;

// edge_index may arrive as int64 (reference declares int64) or int32 (default
// JAX x64-disabled). Detected at runtime.
__device__ __forceinline__ int edge_at(const void* p, long long idx) {
  if (g_is64) return (int)((const long long*)p)[idx];
  return ((const int*)p)[idx];
}

// ---------------- init: dtype detect + zero deg + zero dot accumulators ----
__global__ void init_kernel(const void* __restrict__ eidx) {
  int t = blockIdx.x * blockDim.x + threadIdx.x;
  if (t == 0) {
    const int* p = (const int*)eidx;
    int is64 = 1;
    for (int i = 0; i < 64; ++i) {
      if (p[2 * i + 1] != 0) { is64 = 0; break; }
    }
    g_is64 = is64;
  }
  for (int i = t; i < NMAX; i += gridDim.x * blockDim.x) {
    g_deg[i] = 0;
    g_alsA[i] = 0.f; g_aldA[i] = 0.f;
    g_alsB[i] = 0.f; g_aldB[i] = 0.f;
    g_alsC[i] = 0.f; g_aldC[i] = 0.f;
  }
}

__global__ void hist_kernel(const void* __restrict__ eidx, int E) {
  int t = blockIdx.x * blockDim.x + threadIdx.x;
  if (t >= E) return;
  int d = edge_at(eidx, (long long)E + t);
  atomicAdd(&g_deg[d], 1);
}

__global__ void scan_kernel(int N) {
  const int T = 1024;
  int t = threadIdx.x;
  int per = (N + T - 1) / T;
  int lo = t * per;
  int hi = min(lo + per, N);
  int s = 0;
  for (int i = lo; i < hi; ++i) s += g_deg[i] + 1;  // +1 self loop
  __shared__ int sh[T];
  sh[t] = s;
  __syncthreads();
  for (int off = 1; off < T; off <<= 1) {
    int v = (t >= off) ? sh[t - off] : 0;
    __syncthreads();
    sh[t] += v;
    __syncthreads();
  }
  int run = (t == 0) ? 0 : sh[t - 1];
  for (int i = lo; i < hi; ++i) {
    g_rowptr[i] = run;
    g_cursor[i] = run;
    run += g_deg[i] + 1;
  }
  if (hi == N) { g_rowptr[N] = run; g_cursor[N] = run; }
}

__global__ void scatter_kernel(const void* __restrict__ eidx, int E, int N) {
  int t = blockIdx.x * blockDim.x + threadIdx.x;
  if (t < E) {
    int s = edge_at(eidx, t);
    int d = edge_at(eidx, (long long)E + t);
    int pos = atomicAdd(&g_cursor[d], 1);
    g_srcs[pos] = s;
  } else if (t < E + N) {
    int nd = t - E;                     // self loop
    int pos = atomicAdd(&g_cursor[nd], 1);
    g_srcs[pos] = nd;
  }
}

// ---------------- TF32 tensor-core GEMM + fused attention dots -------------
// C(bf16x2)[N,M] = A[N,K] * W[K,M]; also atomically accumulates the fp32
// dots als = C@a_src, ald = C@a_dst into pre-zeroed arrays.
// 128x128 block tile, BK=32, 256 threads = 8 warps (2x4), warp tile 64x32.
//
// Smem tiles are stored in FRAGMENT-MAJOR layout: each element is scattered
// at staging time to the (lane, reg) slot of the m16n8k8 fragment it feeds.
// Mainloop then loads each A fragment with one LDS.128 and each B fragment
// pair with one LDS.64 -> 8 LDS per 8-k step (vs 24 scalar LDS), and the
// lane*16B / lane*8B access pattern is bank-conflict-free by construction.
//
// m16n8k8 fragment maps (r = lane>>2, c = lane&3):
//   A (row-major): a0=(r,c) a1=(r+8,c) a2=(r,c+4) a3=(r+8,c+4)
//     element (row,col): lane=(row&7)*4+(col&3), reg=(row>>3)+2*(col>>2)
//   B (col-major): b0=(k=c, n=r) b1=(k=c+4, n=r)
//     element (k,n):  lane=(n&7)*4+(k&3),  reg=k>>2

__device__ __forceinline__ unsigned f2tf(float x) {
  unsigned u;
  asm("cvt.rna.tf32.f32 %0, %1;" : "=r"(u) : "f"(x));
  return u;
}

__device__ __forceinline__ unsigned pack_bf16(float lo, float hi) {
  unsigned u;
  asm("cvt.rn.bf16x2.f32 %0, %1, %2;" : "=r"(u) : "f"(hi), "f"(lo));
  return u;
}

__device__ __forceinline__ void mma_tf32(float c[4],
                                         unsigned a0, unsigned a1,
                                         unsigned a2, unsigned a3,
                                         unsigned b0, unsigned b1) {
  asm volatile(
      "mma.sync.aligned.m16n8k8.row.col.f32.tf32.tf32.f32 "
      "{%0,%1,%2,%3}, {%4,%5,%6,%7}, {%8,%9}, {%0,%1,%2,%3};"
      : "+f"(c[0]), "+f"(c[1]), "+f"(c[2]), "+f"(c[3])
      : "r"(a0), "r"(a1), "r"(a2), "r"(a3), "r"(b0), "r"(b1));
}

__global__ __launch_bounds__(256) void gemm_tc_kernel(
    const float* __restrict__ A, const float* __restrict__ W,
    unsigned* __restrict__ C,              // bf16x2 packed, M/2 words per row
    const float* __restrict__ avs, const float* __restrict__ avd,
    float* __restrict__ als, float* __restrict__ ald,
    int N, int K, int M) {
  // Asf[wmi][ks][i][lane][4 regs] : 2*4*4*32*4 = 4096 words (16 KB)
  // Bsf[wnj][ks][j][lane][2 regs] : 4*4*4*32*2 = 4096 words (16 KB)
  __shared__ unsigned Asf[4096];
  __shared__ unsigned Bsf[4096];
  const int bm = blockIdx.y * 128;
  const int bn = blockIdx.x * 128;
  const int tid = threadIdx.x;
  const int warp = tid >> 5, lane = tid & 31;
  const int wmi = warp >> 2;         // warp M half: 0 or 1 (wm = wmi*64)
  const int wnj = warp & 3;          // warp N quarter (wn = wnj*32)
  const int lr = lane >> 2;          // 0..7
  const int lc = lane & 3;           // 0..3

  const int arow = tid >> 1;         // 0..127  (A-tile row this thread loads)
  const int acb  = (tid & 1) * 4;    // A float4-chunk base: 0 or 4
  const int brow = tid >> 3;         // 0..31   (B-tile k-row)
  const int bc4  = tid & 7;          // B float4-col base

  // A staging constants: element (arow, k=(acb+c)*4+e)
  const int a_wmi = arow >> 6;
  const int a_i   = (arow & 63) >> 4;
  const int a_row = arow & 15;
  const int a_lb  = (a_row & 7) * 4;   // lane base (e adds 0..3)
  const int a_rh  = a_row >> 3;        // reg half
  // B staging constants: element (k=brow, n=bn+bc4*4+j32*32+e)
  const int b_ks  = brow >> 3;
  const int b_kc  = brow & 7;
  const int b_reg = b_kc >> 2;
  const int b_lk  = b_kc & 3;
  const int b_j   = bc4 >> 1;
  const int b_nr4 = (bc4 & 1) * 4;

  const bool rok = (bm + arow) < N;
  const float* Arow = A + (size_t)(bm + arow) * K;

  float acc[4][4][4];
#pragma unroll
  for (int i = 0; i < 4; ++i)
#pragma unroll
    for (int j = 0; j < 4; ++j)
#pragma unroll
      for (int q = 0; q < 4; ++q) acc[i][j][q] = 0.f;

  // prologue: load k0=0 tile into registers
  float4 ra[4], rb[4];
#pragma unroll
  for (int c = 0; c < 4; ++c)
    ra[c] = rok ? *(const float4*)(Arow + (acb + c) * 4)
                : make_float4(0.f, 0.f, 0.f, 0.f);
  {
    const float* Wrow = W + (size_t)brow * M + bn;
#pragma unroll
    for (int j = 0; j < 4; ++j)
      rb[j] = *(const float4*)(Wrow + bc4 * 4 + j * 32);
  }

  for (int k0 = 0; k0 < K; k0 += 32) {
    // ---- commit staged registers to smem in fragment-major layout ----
#pragma unroll
    for (int c = 0; c < 4; ++c) {
      int kc4 = acb + c;                 // k = kc4*4 + e
      int ks = kc4 >> 1;
      int reg = a_rh + 2 * (kc4 & 1);
      unsigned* dst =
          &Asf[(((a_wmi * 4 + ks) * 4 + a_i) * 32 + a_lb) * 4 + reg];
      dst[0]  = f2tf(ra[c].x);           // e=0 -> lane+0
      dst[4]  = f2tf(ra[c].y);           // e=1 -> lane+1
      dst[8]  = f2tf(ra[c].z);
      dst[12] = f2tf(ra[c].w);
    }
#pragma unroll
    for (int j32 = 0; j32 < 4; ++j32) {
      unsigned* dst =
          &Bsf[(((j32 * 4 + b_ks) * 4 + b_j) * 32 + b_nr4 + 0) * 2 + b_reg];
      // lane = b_nr4 + b_lk? No: lane = nr*4 + (kc&3); nr = b_nr4/4 + e
      // word idx = (frag*32 + (b_nr4 + e... )) -- recompute exactly:
      // lane(e) = ((bc4&1)*4 + e)*4 + b_lk ; we fold: base covers e=0
      dst += b_lk * 2 - b_nr4 * 2 + (b_nr4 * 4 + b_lk) * 0;  // (no-op; see below)
      unsigned* d2 =
          &Bsf[(((j32 * 4 + b_ks) * 4 + b_j) * 32 + (b_nr4 * 4 + b_lk) / 1) * 0];
      (void)d2;
      // Direct form:
      unsigned* p =
          &Bsf[(((j32 * 4 + b_ks) * 4 + b_j) * 32 + ((bc4 & 1) * 4) * 4 + b_lk) * 2 +
               b_reg];
      p[0 * 8] = f2tf(rb[j32].x);        // e=0: lane += 0  -> +0 words
      p[1 * 8] = f2tf(rb[j32].y);        // e=1: lane += 4  -> +8 words
      p[2 * 8] = f2tf(rb[j32].z);
      p[3 * 8] = f2tf(rb[j32].w);
    }
    __syncthreads();

    // prefetch next tile (overlaps with mma below)
    if (k0 + 32 < K) {
#pragma unroll
      for (int c = 0; c < 4; ++c)
        ra[c] = rok ? *(const float4*)(Arow + k0 + 32 + (acb + c) * 4)
                    : make_float4(0.f, 0.f, 0.f, 0.f);
      const float* Wrow = W + (size_t)(k0 + 32 + brow) * M + bn;
#pragma unroll
      for (int j = 0; j < 4; ++j)
        rb[j] = *(const float4*)(Wrow + bc4 * 4 + j * 32);
    }

    // ---- mainloop: vector fragment loads + MMA ----
#pragma unroll
    for (int ks = 0; ks < 4; ++ks) {
      uint4 af[4];
      uint2 bf[4];
#pragma unroll
      for (int i = 0; i < 4; ++i)
        af[i] = *(const uint4*)&Asf[((wmi * 4 + ks) * 4 + i) * 128 + lane * 4];
#pragma unroll
      for (int j = 0; j < 4; ++j)
        bf[j] = *(const uint2*)&Bsf[((wnj * 4 + ks) * 4 + j) * 64 + lane * 2];
#pragma unroll
      for (int i = 0; i < 4; ++i)
#pragma unroll
        for (int j = 0; j < 4; ++j)
          mma_tf32(acc[i][j], af[i].x, af[i].y, af[i].z, af[i].w,
                   bf[j].x, bf[j].y);
    }
    __syncthreads();
  }

  // ---- epilogue: bf16x2 stores + fused a_src/a_dst dot partials (fp32) ----
  const int wm = wmi * 64;
  const int wn = wnj * 32;
  float avsv[4][2], avdv[4][2];
#pragma unroll
  for (int j = 0; j < 4; ++j) {
    int cb = bn + wn + j * 8 + lc * 2;
    avsv[j][0] = avs[cb]; avsv[j][1] = avs[cb + 1];
    avdv[j][0] = avd[cb]; avdv[j][1] = avd[cb + 1];
  }

  const int Mw = M >> 1;  // words per row
#pragma unroll
  for (int i = 0; i < 4; ++i) {
    int r0 = bm + wm + i * 16 + lr;
    float s0 = 0.f, d0 = 0.f, s1 = 0.f, d1 = 0.f;
#pragma unroll
    for (int j = 0; j < 4; ++j) {
      int cb = bn + wn + j * 8 + lc * 2;
      if (r0 < N)
        C[(size_t)r0 * Mw + (cb >> 1)] = pack_bf16(acc[i][j][0], acc[i][j][1]);
      if (r0 + 8 < N)
        C[(size_t)(r0 + 8) * Mw + (cb >> 1)] =
            pack_bf16(acc[i][j][2], acc[i][j][3]);
      s0 = fmaf(avsv[j][0], acc[i][j][0], fmaf(avsv[j][1], acc[i][j][1], s0));
      d0 = fmaf(avdv[j][0], acc[i][j][0], fmaf(avdv[j][1], acc[i][j][1], d0));
      s1 = fmaf(avsv[j][0], acc[i][j][2], fmaf(avsv[j][1], acc[i][j][3], s1));
      d1 = fmaf(avdv[j][0], acc[i][j][2], fmaf(avdv[j][1], acc[i][j][3], d1));
    }
    // reduce across the 4 lanes (lc = 0..3) sharing each row
#pragma unroll
    for (int o = 1; o < 4; o <<= 1) {
      s0 += __shfl_xor_sync(0xffffffffu, s0, o);
      d0 += __shfl_xor_sync(0xffffffffu, d0, o);
      s1 += __shfl_xor_sync(0xffffffffu, s1, o);
      d1 += __shfl_xor_sync(0xffffffffu, d1, o);
    }
    if (lc == 0) {
      if (r0 < N)     { atomicAdd(&als[r0], s0);     atomicAdd(&ald[r0], d0); }
      if (r0 + 8 < N) { atomicAdd(&als[r0 + 8], s1); atomicAdd(&ald[r0 + 8], d1); }
    }
  }
}

// bf16 bit-exact unpack (bf16 is truncated fp32): 2 ALU ops per pair
__device__ __forceinline__ float blo(unsigned u) { return __uint_as_float(u << 16); }
__device__ __forceinline__ float bhi(unsigned u) { return __uint_as_float(u & 0xffff0000u); }

// ---------------- softmax attention + aggregation (one warp per dst node) ----
// h is packed bf16x2. Register-resident e/exp for deg <= 64; global-scratch
// fallback for larger degrees (impossible for this dataset: Poisson(10)+1).
template <int M, bool RELU>
__global__ __launch_bounds__(256) void attn_agg_kernel(
    const unsigned* __restrict__ h, const float* __restrict__ bias,
    float* __restrict__ out,
    const float* __restrict__ als, const float* __restrict__ ald, int N) {
  int node = (blockIdx.x * blockDim.x + threadIdx.x) >> 5;
  int lane = threadIdx.x & 31;
  if (node >= N) return;
  int beg = g_rowptr[node];
  int end = g_rowptr[node + 1];
  int deg = end - beg;
  float aldn = ald[node];

  constexpr int Mw = M >> 1;        // words per row
  constexpr int NW = Mw / 32;       // words per lane: 4 (M=256) or 2 (M=128)
  float acc[NW * 2];
#pragma unroll
  for (int q = 0; q < NW * 2; ++q) acc[q] = 0.f;

  if (deg <= 64) {
    // ---- fused register path ----
    int s0 = 0, s1 = 0;
    float e0 = -1e30f, e1 = -1e30f;
    if (lane < deg) {
      s0 = g_srcs[beg + lane];
      float e = als[s0] + aldn;
      e0 = (e > 0.f) ? e : 0.2f * e;
    }
    if (32 + lane < deg) {
      s1 = g_srcs[beg + 32 + lane];
      float e = als[s1] + aldn;
      e1 = (e > 0.f) ? e : 0.2f * e;
    }
    float mx = fmaxf(e0, e1);
#pragma unroll
    for (int o = 16; o; o >>= 1)
      mx = fmaxf(mx, __shfl_xor_sync(0xffffffffu, mx, o));
    float ex0 = (lane < deg) ? __expf(e0 - mx) : 0.f;
    float ex1 = (32 + lane < deg) ? __expf(e1 - mx) : 0.f;
    float sum = ex0 + ex1;
#pragma unroll
    for (int o = 16; o; o >>= 1)
      sum += __shfl_xor_sync(0xffffffffu, sum, o);
    float inv = 1.f / sum;

    int jj = 0;
    for (; jj + 2 <= deg; jj += 2) {
      int   ls0 = __shfl_sync(0xffffffffu, (jj < 32) ? s0 : s1, jj & 31);
      float le0 = __shfl_sync(0xffffffffu, (jj < 32) ? ex0 : ex1, jj & 31);
      int   ls1 = __shfl_sync(0xffffffffu, (jj + 1 < 32) ? s0 : s1, (jj + 1) & 31);
      float le1 = __shfl_sync(0xffffffffu, (jj + 1 < 32) ? ex0 : ex1, (jj + 1) & 31);
      float al0 = le0 * inv, al1 = le1 * inv;
      unsigned w0[NW], w1[NW];
      if (NW == 4) {
        uint4 u0 = __ldg((const uint4*)(h + (size_t)ls0 * Mw) + lane);
        uint4 u1 = __ldg((const uint4*)(h + (size_t)ls1 * Mw) + lane);
        w0[0] = u0.x; w0[1] = u0.y; w0[2] = u0.z; w0[3] = u0.w;
        w1[0] = u1.x; w1[1] = u1.y; w1[2] = u1.z; w1[3] = u1.w;
      } else {
        uint2 u0 = __ldg((const uint2*)(h + (size_t)ls0 * Mw) + lane);
        uint2 u1 = __ldg((const uint2*)(h + (size_t)ls1 * Mw) + lane);
        w0[0] = u0.x; w0[1] = u0.y;
        w1[0] = u1.x; w1[1] = u1.y;
      }
#pragma unroll
      for (int q = 0; q < NW; ++q) {
        acc[2 * q + 0] = fmaf(al0, blo(w0[q]), fmaf(al1, blo(w1[q]), acc[2 * q + 0]));
        acc[2 * q + 1] = fmaf(al0, bhi(w0[q]), fmaf(al1, bhi(w1[q]), acc[2 * q + 1]));
      }
    }
    if (jj < deg) {
      int   ls0 = __shfl_sync(0xffffffffu, (jj < 32) ? s0 : s1, jj & 31);
      float le0 = __shfl_sync(0xffffffffu, (jj < 32) ? ex0 : ex1, jj & 31);
      float al0 = le0 * inv;
      unsigned w0[NW];
      if (NW == 4) {
        uint4 u0 = __ldg((const uint4*)(h + (size_t)ls0 * Mw) + lane);
        w0[0] = u0.x; w0[1] = u0.y; w0[2] = u0.z; w0[3] = u0.w;
      } else {
        uint2 u0 = __ldg((const uint2*)(h + (size_t)ls0 * Mw) + lane);
        w0[0] = u0.x; w0[1] = u0.y;
      }
#pragma unroll
      for (int q = 0; q < NW; ++q) {
        acc[2 * q + 0] = fmaf(al0, blo(w0[q]), acc[2 * q + 0]);
        acc[2 * q + 1] = fmaf(al0, bhi(w0[q]), acc[2 * q + 1]);
      }
    }
  } else {
    // ---- fallback: global scratch (rare / impossible for this dataset) ----
    float mx = -1e30f;
    for (int j = beg + lane; j < end; j += 32) {
      float e = als[g_srcs[j]] + aldn;
      e = (e > 0.f) ? e : 0.2f * e;
      g_escr[j] = e;
      mx = fmaxf(mx, e);
    }
#pragma unroll
    for (int o = 16; o; o >>= 1)
      mx = fmaxf(mx, __shfl_xor_sync(0xffffffffu, mx, o));
    float sum = 0.f;
    for (int j = beg + lane; j < end; j += 32) {
      float ex = __expf(g_escr[j] - mx);
      g_escr[j] = ex;
      sum += ex;
    }
#pragma unroll
    for (int o = 16; o; o >>= 1)
      sum += __shfl_xor_sync(0xffffffffu, sum, o);
    float inv = 1.f / sum;
    __syncwarp();
    for (int j = beg; j < end; ++j) {
      float al = g_escr[j] * inv;
      unsigned w0[NW];
      if (NW == 4) {
        uint4 u0 = __ldg((const uint4*)(h + (size_t)g_srcs[j] * Mw) + lane);
        w0[0] = u0.x; w0[1] = u0.y; w0[2] = u0.z; w0[3] = u0.w;
      } else {
        uint2 u0 = __ldg((const uint2*)(h + (size_t)g_srcs[j] * Mw) + lane);
        w0[0] = u0.x; w0[1] = u0.y;
      }
#pragma unroll
      for (int q = 0; q < NW; ++q) {
        acc[2 * q + 0] = fmaf(al, blo(w0[q]), acc[2 * q + 0]);
        acc[2 * q + 1] = fmaf(al, bhi(w0[q]), acc[2 * q + 1]);
      }
    }
  }

  // lane covers columns [lane*2*NW, lane*2*NW + 2*NW)
  float* orow = out + (size_t)node * M + lane * 2 * NW;
  const float* brow = bias + lane * 2 * NW;
#pragma unroll
  for (int q = 0; q < 2 * NW; q += 4) {
    float4 b = *(const float4*)(brow + q);
    float4 r = make_float4(acc[q] + b.x, acc[q + 1] + b.y,
                           acc[q + 2] + b.z, acc[q + 3] + b.w);
    if (RELU) {
      r.x = fmaxf(r.x, 0.f); r.y = fmaxf(r.y, 0.f);
      r.z = fmaxf(r.z, 0.f); r.w = fmaxf(r.w, 0.f);
    }
    *(float4*)(orow + q) = r;
  }
}

// ---------------- host driver ----------------
extern "C" void kernel_launch(void* const* d_in, const int* in_sizes, int n_in,
                              void* d_out, int out_size) {
  const float* x = (const float*)d_in[0];
  const void* eidx = d_in[1];
  const int base = n_in - 12;
  const float* W1  = (const float*)d_in[base + 0];
  const float* as1 = (const float*)d_in[base + 1];
  const float* ad1 = (const float*)d_in[base + 2];
  const float* b1  = (const float*)d_in[base + 3];
  const float* W2  = (const float*)d_in[base + 4];
  const float* as2 = (const float*)d_in[base + 5];
  const float* ad2 = (const float*)d_in[base + 6];
  const float* b2  = (const float*)d_in[base + 7];
  const float* W3  = (const float*)d_in[base + 8];
  const float* as3 = (const float*)d_in[base + 9];
  const float* ad3 = (const float*)d_in[base + 10];
  const float* b3  = (const float*)d_in[base + 11];

  const int N = in_sizes[0] / 128;
  const int E = in_sizes[1] / 2;

  unsigned* bufA;
  float* bufB;
  float *alsA, *aldA, *alsB, *aldB, *alsC, *aldC;
  cudaGetSymbolAddress((void**)&bufA, g_bufA);
  cudaGetSymbolAddress((void**)&bufB, g_bufB);
  cudaGetSymbolAddress((void**)&alsA, g_alsA);
  cudaGetSymbolAddress((void**)&aldA, g_aldA);
  cudaGetSymbolAddress((void**)&alsB, g_alsB);
  cudaGetSymbolAddress((void**)&aldB, g_aldB);
  cudaGetSymbolAddress((void**)&alsC, g_alsC);
  cudaGetSymbolAddress((void**)&aldC, g_aldC);

  // CSR build (once — shared by all 3 layers) + zero dot accumulators
  init_kernel<<<160, 256>>>(eidx);
  hist_kernel<<<(E + 255) / 256, 256>>>(eidx, E);
  scan_kernel<<<1, 1024>>>(N);
  scatter_kernel<<<(E + N + 255) / 256, 256>>>(eidx, E, N);

  const int gy = (N + 127) / 128;
  const int agg_blocks = (N + 7) / 8;

  // Layer 1: x[N,128] -> h1(bf16)[N,256] (relu after agg)
  gemm_tc_kernel<<<dim3(2, gy), 256>>>(x, W1, bufA, as1, ad1, alsA, aldA, N, 128, 256);
  attn_agg_kernel<256, true><<<agg_blocks, 256>>>(bufA, b1, bufB, alsA, aldA, N);

  // Layer 2: h1agg[N,256] -> h2(bf16)[N,256]
  gemm_tc_kernel<<<dim3(2, gy), 256>>>(bufB, W2, bufA, as2, ad2, alsB, aldB, N, 256, 256);
  attn_agg_kernel<256, true><<<agg_blocks, 256>>>(bufA, b2, bufB, alsB, aldB, N);

  // Layer 3: h2agg[N,256] -> h3(bf16)[N,128] -> out fp32
  gemm_tc_kernel<<<dim3(1, gy), 256>>>(bufB, W3, bufA, as3, ad3, alsC, aldC, N, 256, 128);
  attn_agg_kernel<128, false><<<agg_blocks, 256>>>(bufA, b3, (float*)d_out, alsC, aldC, N);
}

// round 15
// speedup vs baseline: 1.0660x; 1.0660x over previous
#include <cuda_runtime.h>
#include <cuda_bf16.h>
#include <math.h>

// Problem constants (shapes fixed by the reference setup)
#define NMAX   40000
#define EMAX   400000
#define EPRIME (EMAX + NMAX)

// ---------------- device scratch (no allocation allowed) ----------------
// bufA holds h as packed bf16 (M/2 uint32 per row). bufB holds fp32 agg output.
__device__ unsigned g_bufA[NMAX * 128];   // bf16x2: up to 256 cols
__device__ float    g_bufB[NMAX * 256];
__device__ float g_alsA[NMAX], g_aldA[NMAX];
__device__ float g_alsB[NMAX], g_aldB[NMAX];
__device__ float g_alsC[NMAX], g_aldC[NMAX];
__device__ float g_escr[EPRIME];      // fallback scratch for high-degree nodes
__device__ int   g_deg[NMAX];
__device__ int   g_rowptr[NMAX + 1];
__device__ int   g_cursor[NMAX + 1];
__device__ int   g_srcs[EPRIME];      // src node of each dst-sorted edge
__device__ int   g_is64;

// edge_index may arrive as int64 (reference declares int64) or int32 (default
// JAX x64-disabled). Detected at runtime.
__device__ __forceinline__ int edge_at(const void* p, long long idx) {
  if (g_is64) return (int)((const long long*)p)[idx];
  return ((const int*)p)[idx];
}

// ---------------- init: dtype detect + zero deg + zero dot accumulators ----
__global__ void init_kernel(const void* __restrict__ eidx) {
  int t = blockIdx.x * blockDim.x + threadIdx.x;
  if (t == 0) {
    const int* p = (const int*)eidx;
    int is64 = 1;
    for (int i = 0; i < 64; ++i) {
      if (p[2 * i + 1] != 0) { is64 = 0; break; }
    }
    g_is64 = is64;
  }
  for (int i = t; i < NMAX; i += gridDim.x * blockDim.x) {
    g_deg[i] = 0;
    g_alsA[i] = 0.f; g_aldA[i] = 0.f;
    g_alsB[i] = 0.f; g_aldB[i] = 0.f;
    g_alsC[i] = 0.f; g_aldC[i] = 0.f;
  }
}

__global__ void hist_kernel(const void* __restrict__ eidx, int E) {
  int t = blockIdx.x * blockDim.x + threadIdx.x;
  if (t >= E) return;
  int d = edge_at(eidx, (long long)E + t);
  atomicAdd(&g_deg[d], 1);
}

__global__ void scan_kernel(int N) {
  const int T = 1024;
  int t = threadIdx.x;
  int per = (N + T - 1) / T;
  int lo = t * per;
  int hi = min(lo + per, N);
  int s = 0;
  for (int i = lo; i < hi; ++i) s += g_deg[i] + 1;  // +1 self loop
  __shared__ int sh[T];
  sh[t] = s;
  __syncthreads();
  for (int off = 1; off < T; off <<= 1) {
    int v = (t >= off) ? sh[t - off] : 0;
    __syncthreads();
    sh[t] += v;
    __syncthreads();
  }
  int run = (t == 0) ? 0 : sh[t - 1];
  for (int i = lo; i < hi; ++i) {
    g_rowptr[i] = run;
    g_cursor[i] = run;
    run += g_deg[i] + 1;
  }
  if (hi == N) { g_rowptr[N] = run; g_cursor[N] = run; }
}

__global__ void scatter_kernel(const void* __restrict__ eidx, int E, int N) {
  int t = blockIdx.x * blockDim.x + threadIdx.x;
  if (t < E) {
    int s = edge_at(eidx, t);
    int d = edge_at(eidx, (long long)E + t);
    int pos = atomicAdd(&g_cursor[d], 1);
    g_srcs[pos] = s;
  } else if (t < E + N) {
    int nd = t - E;                     // self loop
    int pos = atomicAdd(&g_cursor[nd], 1);
    g_srcs[pos] = nd;
  }
}

// ---------------- TF32 tensor-core GEMM + fused attention dots -------------
// C(bf16x2)[N,M] = A[N,K] * W[K,M]; also atomically accumulates the fp32
// dots als = C@a_src, ald = C@a_dst into pre-zeroed arrays.
// 128x128 block tile, BK=32, 256 threads = 8 warps (2x4), warp tile 64x32.
// R12 layout (linear [k][m]/[k][n] smem, padded 132) + DOUBLE-BUFFERED smem:
// one __syncthreads per k-iteration; staging stores for tile t+1 overlap the
// MMAs of tile t. tf32 conversion at the smem commit (off the MMA path).

__device__ __forceinline__ unsigned f2tf(float x) {
  unsigned u;
  asm("cvt.rna.tf32.f32 %0, %1;" : "=r"(u) : "f"(x));
  return u;
}

__device__ __forceinline__ unsigned pack_bf16(float lo, float hi) {
  unsigned u;
  asm("cvt.rn.bf16x2.f32 %0, %1, %2;" : "=r"(u) : "f"(hi), "f"(lo));
  return u;
}

__device__ __forceinline__ void mma_tf32(float c[4],
                                         unsigned a0, unsigned a1,
                                         unsigned a2, unsigned a3,
                                         unsigned b0, unsigned b1) {
  asm volatile(
      "mma.sync.aligned.m16n8k8.row.col.f32.tf32.tf32.f32 "
      "{%0,%1,%2,%3}, {%4,%5,%6,%7}, {%8,%9}, {%0,%1,%2,%3};"
      : "+f"(c[0]), "+f"(c[1]), "+f"(c[2]), "+f"(c[3])
      : "r"(a0), "r"(a1), "r"(a2), "r"(a3), "r"(b0), "r"(b1));
}

// Per-buffer layout: As tile 32*132 words, Bs tile 32*132 words.
#define GT_TILE  4224            // words per tile (32*132)
#define GT_BUF   (2 * GT_TILE)   // words per buffer (As + Bs)
#define GT_SMEM_BYTES (2 * GT_BUF * 4)

__global__ __launch_bounds__(256) void gemm_tc_kernel(
    const float* __restrict__ A, const float* __restrict__ W,
    unsigned* __restrict__ C,              // bf16x2 packed, M/2 words per row
    const float* __restrict__ avs, const float* __restrict__ avd,
    float* __restrict__ als, float* __restrict__ ald,
    int N, int K, int M) {
  extern __shared__ unsigned gsm[];
  const int bm = blockIdx.y * 128;
  const int bn = blockIdx.x * 128;
  const int tid = threadIdx.x;
  const int warp = tid >> 5, lane = tid & 31;
  const int wm = (warp >> 2) * 64;   // warp M offset: 0 or 64
  const int wn = (warp & 3) * 32;    // warp N offset: 0/32/64/96
  const int lr = lane >> 2;          // 0..7
  const int lc = lane & 3;           // 0..3

  const int arow = tid >> 1;         // 0..127  (A-tile row this thread loads)
  const int acb  = (tid & 1) * 4;    // A float4-chunk base: 0 or 4
  const int brow = tid >> 3;         // 0..31   (B-tile k-row)
  const int bc4  = tid & 7;          // B float4-col base

  const bool rok = (bm + arow) < N;
  const float* Arow = A + (size_t)(bm + arow) * K;

  float acc[4][4][4];
#pragma unroll
  for (int i = 0; i < 4; ++i)
#pragma unroll
    for (int j = 0; j < 4; ++j)
#pragma unroll
      for (int q = 0; q < 4; ++q) acc[i][j][q] = 0.f;

  float4 ra[4], rb[4];
  // prologue: load tile 0 into registers
#pragma unroll
  for (int c = 0; c < 4; ++c)
    ra[c] = rok ? *(const float4*)(Arow + (acb + c) * 4)
                : make_float4(0.f, 0.f, 0.f, 0.f);
  {
    const float* Wrow = W + (size_t)brow * M + bn;
#pragma unroll
    for (int j = 0; j < 4; ++j)
      rb[j] = *(const float4*)(Wrow + bc4 * 4 + j * 32);
  }

  // commit tile 0 to buffer 0
  {
    unsigned* As_ = gsm;
    unsigned* Bs_ = gsm + GT_TILE;
#pragma unroll
    for (int c = 0; c < 4; ++c) {
      int kk = (acb + c) * 4;
      As_[(kk + 0) * 132 + arow] = f2tf(ra[c].x);
      As_[(kk + 1) * 132 + arow] = f2tf(ra[c].y);
      As_[(kk + 2) * 132 + arow] = f2tf(ra[c].z);
      As_[(kk + 3) * 132 + arow] = f2tf(ra[c].w);
    }
#pragma unroll
    for (int j = 0; j < 4; ++j)
      *(uint4*)&Bs_[brow * 132 + bc4 * 4 + j * 32] =
          make_uint4(f2tf(rb[j].x), f2tf(rb[j].y), f2tf(rb[j].z), f2tf(rb[j].w));
  }
  __syncthreads();

  const int nT = K >> 5;
  for (int t = 0; t < nT; ++t) {
    // prefetch tile t+1 into registers (overlaps with MMAs below)
    if (t + 1 < nT) {
      int koff = (t + 1) << 5;
#pragma unroll
      for (int c = 0; c < 4; ++c)
        ra[c] = rok ? *(const float4*)(Arow + koff + (acb + c) * 4)
                    : make_float4(0.f, 0.f, 0.f, 0.f);
      const float* Wrow = W + (size_t)(koff + brow) * M + bn;
#pragma unroll
      for (int j = 0; j < 4; ++j)
        rb[j] = *(const float4*)(Wrow + bc4 * 4 + j * 32);
    }

    // ---- compute on buffer t&1 ----
    const unsigned* As_ = gsm + (t & 1) * GT_BUF;
    const unsigned* Bs_ = As_ + GT_TILE;
#pragma unroll
    for (int ks = 0; ks < 4; ++ks) {
      const int kb = ks * 8;
      unsigned af[4][4], bf[4][2];
#pragma unroll
      for (int i = 0; i < 4; ++i) {
        int m = wm + i * 16 + lr;
        af[i][0] = As_[(kb + lc) * 132 + m];
        af[i][1] = As_[(kb + lc) * 132 + m + 8];
        af[i][2] = As_[(kb + lc + 4) * 132 + m];
        af[i][3] = As_[(kb + lc + 4) * 132 + m + 8];
      }
#pragma unroll
      for (int j = 0; j < 4; ++j) {
        int n = wn + j * 8 + lr;
        bf[j][0] = Bs_[(kb + lc) * 132 + n];
        bf[j][1] = Bs_[(kb + lc + 4) * 132 + n];
      }
#pragma unroll
      for (int i = 0; i < 4; ++i)
#pragma unroll
        for (int j = 0; j < 4; ++j)
          mma_tf32(acc[i][j], af[i][0], af[i][1], af[i][2], af[i][3],
                   bf[j][0], bf[j][1]);
    }

    // ---- commit tile t+1 to the other buffer; single sync ----
    if (t + 1 < nT) {
      unsigned* Aw = gsm + ((t + 1) & 1) * GT_BUF;
      unsigned* Bw = Aw + GT_TILE;
#pragma unroll
      for (int c = 0; c < 4; ++c) {
        int kk = (acb + c) * 4;
        Aw[(kk + 0) * 132 + arow] = f2tf(ra[c].x);
        Aw[(kk + 1) * 132 + arow] = f2tf(ra[c].y);
        Aw[(kk + 2) * 132 + arow] = f2tf(ra[c].z);
        Aw[(kk + 3) * 132 + arow] = f2tf(ra[c].w);
      }
#pragma unroll
      for (int j = 0; j < 4; ++j)
        *(uint4*)&Bw[brow * 132 + bc4 * 4 + j * 32] =
            make_uint4(f2tf(rb[j].x), f2tf(rb[j].y), f2tf(rb[j].z),
                       f2tf(rb[j].w));
      __syncthreads();
    }
  }

  // ---- epilogue: bf16x2 stores + fused a_src/a_dst dot partials (fp32) ----
  float avsv[4][2], avdv[4][2];
#pragma unroll
  for (int j = 0; j < 4; ++j) {
    int cb = bn + wn + j * 8 + lc * 2;
    avsv[j][0] = avs[cb]; avsv[j][1] = avs[cb + 1];
    avdv[j][0] = avd[cb]; avdv[j][1] = avd[cb + 1];
  }

  const int Mw = M >> 1;  // words per row
#pragma unroll
  for (int i = 0; i < 4; ++i) {
    int r0 = bm + wm + i * 16 + lr;
    float s0 = 0.f, d0 = 0.f, s1 = 0.f, d1 = 0.f;
#pragma unroll
    for (int j = 0; j < 4; ++j) {
      int cb = bn + wn + j * 8 + lc * 2;
      if (r0 < N)
        C[(size_t)r0 * Mw + (cb >> 1)] = pack_bf16(acc[i][j][0], acc[i][j][1]);
      if (r0 + 8 < N)
        C[(size_t)(r0 + 8) * Mw + (cb >> 1)] =
            pack_bf16(acc[i][j][2], acc[i][j][3]);
      s0 = fmaf(avsv[j][0], acc[i][j][0], fmaf(avsv[j][1], acc[i][j][1], s0));
      d0 = fmaf(avdv[j][0], acc[i][j][0], fmaf(avdv[j][1], acc[i][j][1], d0));
      s1 = fmaf(avsv[j][0], acc[i][j][2], fmaf(avsv[j][1], acc[i][j][3], s1));
      d1 = fmaf(avdv[j][0], acc[i][j][2], fmaf(avdv[j][1], acc[i][j][3], d1));
    }
    // reduce across the 4 lanes (lc = 0..3) sharing each row
#pragma unroll
    for (int o = 1; o < 4; o <<= 1) {
      s0 += __shfl_xor_sync(0xffffffffu, s0, o);
      d0 += __shfl_xor_sync(0xffffffffu, d0, o);
      s1 += __shfl_xor_sync(0xffffffffu, s1, o);
      d1 += __shfl_xor_sync(0xffffffffu, d1, o);
    }
    if (lc == 0) {
      if (r0 < N)     { atomicAdd(&als[r0], s0);     atomicAdd(&ald[r0], d0); }
      if (r0 + 8 < N) { atomicAdd(&als[r0 + 8], s1); atomicAdd(&ald[r0 + 8], d1); }
    }
  }
}

// bf16 bit-exact unpack (bf16 is truncated fp32): 2 ALU ops per pair
__device__ __forceinline__ float blo(unsigned u) { return __uint_as_float(u << 16); }
__device__ __forceinline__ float bhi(unsigned u) { return __uint_as_float(u & 0xffff0000u); }

// ---------------- softmax attention + aggregation (one warp per dst node) ----
// h is packed bf16x2. Register-resident e/exp for deg <= 64; global-scratch
// fallback for larger degrees (impossible for this dataset: Poisson(10)+1).
template <int M, bool RELU>
__global__ __launch_bounds__(256) void attn_agg_kernel(
    const unsigned* __restrict__ h, const float* __restrict__ bias,
    float* __restrict__ out,
    const float* __restrict__ als, const float* __restrict__ ald, int N) {
  int node = (blockIdx.x * blockDim.x + threadIdx.x) >> 5;
  int lane = threadIdx.x & 31;
  if (node >= N) return;
  int beg = g_rowptr[node];
  int end = g_rowptr[node + 1];
  int deg = end - beg;
  float aldn = ald[node];

  constexpr int Mw = M >> 1;        // words per row
  constexpr int NW = Mw / 32;       // words per lane: 4 (M=256) or 2 (M=128)
  float acc[NW * 2];
#pragma unroll
  for (int q = 0; q < NW * 2; ++q) acc[q] = 0.f;

  if (deg <= 64) {
    // ---- fused register path ----
    int s0 = 0, s1 = 0;
    float e0 = -1e30f, e1 = -1e30f;
    if (lane < deg) {
      s0 = g_srcs[beg + lane];
      float e = als[s0] + aldn;
      e0 = (e > 0.f) ? e : 0.2f * e;
    }
    if (32 + lane < deg) {
      s1 = g_srcs[beg + 32 + lane];
      float e = als[s1] + aldn;
      e1 = (e > 0.f) ? e : 0.2f * e;
    }
    float mx = fmaxf(e0, e1);
#pragma unroll
    for (int o = 16; o; o >>= 1)
      mx = fmaxf(mx, __shfl_xor_sync(0xffffffffu, mx, o));
    float ex0 = (lane < deg) ? __expf(e0 - mx) : 0.f;
    float ex1 = (32 + lane < deg) ? __expf(e1 - mx) : 0.f;
    float sum = ex0 + ex1;
#pragma unroll
    for (int o = 16; o; o >>= 1)
      sum += __shfl_xor_sync(0xffffffffu, sum, o);
    float inv = 1.f / sum;

    int jj = 0;
    for (; jj + 2 <= deg; jj += 2) {
      int   ls0 = __shfl_sync(0xffffffffu, (jj < 32) ? s0 : s1, jj & 31);
      float le0 = __shfl_sync(0xffffffffu, (jj < 32) ? ex0 : ex1, jj & 31);
      int   ls1 = __shfl_sync(0xffffffffu, (jj + 1 < 32) ? s0 : s1, (jj + 1) & 31);
      float le1 = __shfl_sync(0xffffffffu, (jj + 1 < 32) ? ex0 : ex1, (jj + 1) & 31);
      float al0 = le0 * inv, al1 = le1 * inv;
      unsigned w0[NW], w1[NW];
      if (NW == 4) {
        uint4 u0 = __ldg((const uint4*)(h + (size_t)ls0 * Mw) + lane);
        uint4 u1 = __ldg((const uint4*)(h + (size_t)ls1 * Mw) + lane);
        w0[0] = u0.x; w0[1] = u0.y; w0[2] = u0.z; w0[3] = u0.w;
        w1[0] = u1.x; w1[1] = u1.y; w1[2] = u1.z; w1[3] = u1.w;
      } else {
        uint2 u0 = __ldg((const uint2*)(h + (size_t)ls0 * Mw) + lane);
        uint2 u1 = __ldg((const uint2*)(h + (size_t)ls1 * Mw) + lane);
        w0[0] = u0.x; w0[1] = u0.y;
        w1[0] = u1.x; w1[1] = u1.y;
      }
#pragma unroll
      for (int q = 0; q < NW; ++q) {
        acc[2 * q + 0] = fmaf(al0, blo(w0[q]), fmaf(al1, blo(w1[q]), acc[2 * q + 0]));
        acc[2 * q + 1] = fmaf(al0, bhi(w0[q]), fmaf(al1, bhi(w1[q]), acc[2 * q + 1]));
      }
    }
    if (jj < deg) {
      int   ls0 = __shfl_sync(0xffffffffu, (jj < 32) ? s0 : s1, jj & 31);
      float le0 = __shfl_sync(0xffffffffu, (jj < 32) ? ex0 : ex1, jj & 31);
      float al0 = le0 * inv;
      unsigned w0[NW];
      if (NW == 4) {
        uint4 u0 = __ldg((const uint4*)(h + (size_t)ls0 * Mw) + lane);
        w0[0] = u0.x; w0[1] = u0.y; w0[2] = u0.z; w0[3] = u0.w;
      } else {
        uint2 u0 = __ldg((const uint2*)(h + (size_t)ls0 * Mw) + lane);
        w0[0] = u0.x; w0[1] = u0.y;
      }
#pragma unroll
      for (int q = 0; q < NW; ++q) {
        acc[2 * q + 0] = fmaf(al0, blo(w0[q]), acc[2 * q + 0]);
        acc[2 * q + 1] = fmaf(al0, bhi(w0[q]), acc[2 * q + 1]);
      }
    }
  } else {
    // ---- fallback: global scratch (rare / impossible for this dataset) ----
    float mx = -1e30f;
    for (int j = beg + lane; j < end; j += 32) {
      float e = als[g_srcs[j]] + aldn;
      e = (e > 0.f) ? e : 0.2f * e;
      g_escr[j] = e;
      mx = fmaxf(mx, e);
    }
#pragma unroll
    for (int o = 16; o; o >>= 1)
      mx = fmaxf(mx, __shfl_xor_sync(0xffffffffu, mx, o));
    float sum = 0.f;
    for (int j = beg + lane; j < end; j += 32) {
      float ex = __expf(g_escr[j] - mx);
      g_escr[j] = ex;
      sum += ex;
    }
#pragma unroll
    for (int o = 16; o; o >>= 1)
      sum += __shfl_xor_sync(0xffffffffu, sum, o);
    float inv = 1.f / sum;
    __syncwarp();
    for (int j = beg; j < end; ++j) {
      float al = g_escr[j] * inv;
      unsigned w0[NW];
      if (NW == 4) {
        uint4 u0 = __ldg((const uint4*)(h + (size_t)g_srcs[j] * Mw) + lane);
        w0[0] = u0.x; w0[1] = u0.y; w0[2] = u0.z; w0[3] = u0.w;
      } else {
        uint2 u0 = __ldg((const uint2*)(h + (size_t)g_srcs[j] * Mw) + lane);
        w0[0] = u0.x; w0[1] = u0.y;
      }
#pragma unroll
      for (int q = 0; q < NW; ++q) {
        acc[2 * q + 0] = fmaf(al, blo(w0[q]), acc[2 * q + 0]);
        acc[2 * q + 1] = fmaf(al, bhi(w0[q]), acc[2 * q + 1]);
      }
    }
  }

  // lane covers columns [lane*2*NW, lane*2*NW + 2*NW)
  float* orow = out + (size_t)node * M + lane * 2 * NW;
  const float* brow = bias + lane * 2 * NW;
#pragma unroll
  for (int q = 0; q < 2 * NW; q += 4) {
    float4 b = *(const float4*)(brow + q);
    float4 r = make_float4(acc[q] + b.x, acc[q + 1] + b.y,
                           acc[q + 2] + b.z, acc[q + 3] + b.w);
    if (RELU) {
      r.x = fmaxf(r.x, 0.f); r.y = fmaxf(r.y, 0.f);
      r.z = fmaxf(r.z, 0.f); r.w = fmaxf(r.w, 0.f);
    }
    *(float4*)(orow + q) = r;
  }
}

// ---------------- host driver ----------------
extern "C" void kernel_launch(void* const* d_in, const int* in_sizes, int n_in,
                              void* d_out, int out_size) {
  const float* x = (const float*)d_in[0];
  const void* eidx = d_in[1];
  const int base = n_in - 12;
  const float* W1  = (const float*)d_in[base + 0];
  const float* as1 = (const float*)d_in[base + 1];
  const float* ad1 = (const float*)d_in[base + 2];
  const float* b1  = (const float*)d_in[base + 3];
  const float* W2  = (const float*)d_in[base + 4];
  const float* as2 = (const float*)d_in[base + 5];
  const float* ad2 = (const float*)d_in[base + 6];
  const float* b2  = (const float*)d_in[base + 7];
  const float* W3  = (const float*)d_in[base + 8];
  const float* as3 = (const float*)d_in[base + 9];
  const float* ad3 = (const float*)d_in[base + 10];
  const float* b3  = (const float*)d_in[base + 11];

  const int N = in_sizes[0] / 128;
  const int E = in_sizes[1] / 2;

  unsigned* bufA;
  float* bufB;
  float *alsA, *aldA, *alsB, *aldB, *alsC, *aldC;
  cudaGetSymbolAddress((void**)&bufA, g_bufA);
  cudaGetSymbolAddress((void**)&bufB, g_bufB);
  cudaGetSymbolAddress((void**)&alsA, g_alsA);
  cudaGetSymbolAddress((void**)&aldA, g_aldA);
  cudaGetSymbolAddress((void**)&alsB, g_alsB);
  cudaGetSymbolAddress((void**)&aldB, g_aldB);
  cudaGetSymbolAddress((void**)&alsC, g_alsC);
  cudaGetSymbolAddress((void**)&aldC, g_aldC);

  // 66 KB dynamic smem for the double-buffered GEMM (attribute set is
  // idempotent; not a stream op, safe under graph capture)
  cudaFuncSetAttribute(gemm_tc_kernel,
                       cudaFuncAttributeMaxDynamicSharedMemorySize,
                       GT_SMEM_BYTES);

  // CSR build (once — shared by all 3 layers) + zero dot accumulators
  init_kernel<<<160, 256>>>(eidx);
  hist_kernel<<<(E + 255) / 256, 256>>>(eidx, E);
  scan_kernel<<<1, 1024>>>(N);
  scatter_kernel<<<(E + N + 255) / 256, 256>>>(eidx, E, N);

  const int gy = (N + 127) / 128;
  const int agg_blocks = (N + 7) / 8;

  // Layer 1: x[N,128] -> h1(bf16)[N,256] (relu after agg)
  gemm_tc_kernel<<<dim3(2, gy), 256, GT_SMEM_BYTES>>>(
      x, W1, bufA, as1, ad1, alsA, aldA, N, 128, 256);
  attn_agg_kernel<256, true><<<agg_blocks, 256>>>(bufA, b1, bufB, alsA, aldA, N);

  // Layer 2: h1agg[N,256] -> h2(bf16)[N,256]
  gemm_tc_kernel<<<dim3(2, gy), 256, GT_SMEM_BYTES>>>(
      bufB, W2, bufA, as2, ad2, alsB, aldB, N, 256, 256);
  attn_agg_kernel<256, true><<<agg_blocks, 256>>>(bufA, b2, bufB, alsB, aldB, N);

  // Layer 3: h2agg[N,256] -> h3(bf16)[N,128] -> out fp32
  gemm_tc_kernel<<<dim3(1, gy), 256, GT_SMEM_BYTES>>>(
      bufB, W3, bufA, as3, ad3, alsC, aldC, N, 256, 128);
  attn_agg_kernel<128, false><<<agg_blocks, 256>>>(bufA, b3, (float*)d_out, alsC, aldC, N);
}

// round 16
// speedup vs baseline: 1.1144x; 1.0453x over previous
#include <cuda_runtime.h>
#include <cuda_bf16.h>
#include <math.h>

// Problem constants (shapes fixed by the reference setup)
#define NMAX   40000
#define EMAX   400000
#define EPRIME (EMAX + NMAX)

// ---------------- device scratch (no allocation allowed) ----------------
// bufA holds h as packed bf16 (M/2 uint32 per row). bufB holds fp32 agg output.
__device__ unsigned g_bufA[NMAX * 128];   // bf16x2: up to 256 cols
__device__ float    g_bufB[NMAX * 256];
__device__ float g_alsA[NMAX], g_aldA[NMAX];
__device__ float g_alsB[NMAX], g_aldB[NMAX];
__device__ float g_alsC[NMAX], g_aldC[NMAX];
__device__ float g_escr[EPRIME];      // fallback scratch for high-degree nodes
__device__ int   g_deg[NMAX];
__device__ int   g_rowptr[NMAX + 1];
__device__ int   g_cursor[NMAX + 1];
__device__ int   g_srcs[EPRIME];      // src node of each dst-sorted edge
__device__ int   g_is64;

// edge_index may arrive as int64 (reference declares int64) or int32 (default
// JAX x64-disabled). Detected at runtime.
__device__ __forceinline__ int edge_at(const void* p, long long idx) {
  if (g_is64) return (int)((const long long*)p)[idx];
  return ((const int*)p)[idx];
}

// ---------------- init: dtype detect + zero deg + zero dot accumulators ----
__global__ void init_kernel(const void* __restrict__ eidx) {
  int t = blockIdx.x * blockDim.x + threadIdx.x;
  if (t == 0) {
    const int* p = (const int*)eidx;
    int is64 = 1;
    for (int i = 0; i < 64; ++i) {
      if (p[2 * i + 1] != 0) { is64 = 0; break; }
    }
    g_is64 = is64;
  }
  for (int i = t; i < NMAX; i += gridDim.x * blockDim.x) {
    g_deg[i] = 0;
    g_alsA[i] = 0.f; g_aldA[i] = 0.f;
    g_alsB[i] = 0.f; g_aldB[i] = 0.f;
    g_alsC[i] = 0.f; g_aldC[i] = 0.f;
  }
}

// ---- hist: 4 edges per thread, 16B vector loads ----
__global__ void hist_kernel(const void* __restrict__ eidx, int E) {
  int t = blockIdx.x * blockDim.x + threadIdx.x;
  int b = t * 4;
  if (b >= E) return;
  int d[4];
  int n = min(4, E - b);
  if (n == 4) {
    if (g_is64) {
      const longlong2* p = (const longlong2*)eidx;  // dst at idx E+b
      longlong2 u0 = p[(E + b) >> 1];
      longlong2 u1 = p[((E + b) >> 1) + 1];
      d[0] = (int)u0.x; d[1] = (int)u0.y; d[2] = (int)u1.x; d[3] = (int)u1.y;
    } else {
      int4 u = *(const int4*)((const int*)eidx + E + b);
      d[0] = u.x; d[1] = u.y; d[2] = u.z; d[3] = u.w;
    }
  } else {
    for (int i = 0; i < n; ++i) d[i] = edge_at(eidx, (long long)E + b + i);
  }
  for (int i = 0; i < n; ++i) atomicAdd(&g_deg[d[i]], 1);
}

__global__ void scan_kernel(int N) {
  const int T = 1024;
  int t = threadIdx.x;
  int per = (N + T - 1) / T;
  int lo = t * per;
  int hi = min(lo + per, N);
  int s = 0;
  for (int i = lo; i < hi; ++i) s += g_deg[i] + 1;  // +1 self loop
  __shared__ int sh[T];
  sh[t] = s;
  __syncthreads();
  for (int off = 1; off < T; off <<= 1) {
    int v = (t >= off) ? sh[t - off] : 0;
    __syncthreads();
    sh[t] += v;
    __syncthreads();
  }
  int run = (t == 0) ? 0 : sh[t - 1];
  for (int i = lo; i < hi; ++i) {
    g_rowptr[i] = run;
    g_cursor[i] = run;
    run += g_deg[i] + 1;
  }
  if (hi == N) { g_rowptr[N] = run; g_cursor[N] = run; }
}

// ---- scatter: 4 edges per thread, 16B vector loads; then self loops ----
__global__ void scatter_kernel(const void* __restrict__ eidx, int E, int N) {
  int t = blockIdx.x * blockDim.x + threadIdx.x;
  int quads = (E + 3) >> 2;
  if (t < quads) {
    int b = t * 4;
    int n = min(4, E - b);
    int s[4], d[4];
    if (n == 4) {
      if (g_is64) {
        const longlong2* p = (const longlong2*)eidx;
        longlong2 s0 = p[b >> 1], s1 = p[(b >> 1) + 1];
        longlong2 d0 = p[(E + b) >> 1], d1 = p[((E + b) >> 1) + 1];
        s[0] = (int)s0.x; s[1] = (int)s0.y; s[2] = (int)s1.x; s[3] = (int)s1.y;
        d[0] = (int)d0.x; d[1] = (int)d0.y; d[2] = (int)d1.x; d[3] = (int)d1.y;
      } else {
        int4 su = *(const int4*)((const int*)eidx + b);
        int4 du = *(const int4*)((const int*)eidx + E + b);
        s[0] = su.x; s[1] = su.y; s[2] = su.z; s[3] = su.w;
        d[0] = du.x; d[1] = du.y; d[2] = du.z; d[3] = du.w;
      }
    } else {
      for (int i = 0; i < n; ++i) {
        s[i] = edge_at(eidx, b + i);
        d[i] = edge_at(eidx, (long long)E + b + i);
      }
    }
    for (int i = 0; i < n; ++i) {
      int pos = atomicAdd(&g_cursor[d[i]], 1);
      g_srcs[pos] = s[i];
    }
  } else if (t - quads < N) {
    int nd = t - quads;                 // self loop
    int pos = atomicAdd(&g_cursor[nd], 1);
    g_srcs[pos] = nd;
  }
}

// ---------------- TF32 tensor-core GEMM + fused attention dots -------------
// (Exact R12 configuration: 128x128 block tile, BK=32, 256 threads = 8 warps
// (2x4), warp tile 64x32, static smem [k][m]/[k][n] padded 132, register
// double-buffered global loads, tf32 cvt at smem commit, two syncs/iter.)

__device__ __forceinline__ unsigned f2tf(float x) {
  unsigned u;
  asm("cvt.rna.tf32.f32 %0, %1;" : "=r"(u) : "f"(x));
  return u;
}

__device__ __forceinline__ unsigned pack_bf16(float lo, float hi) {
  unsigned u;
  asm("cvt.rn.bf16x2.f32 %0, %1, %2;" : "=r"(u) : "f"(hi), "f"(lo));
  return u;
}

__device__ __forceinline__ void mma_tf32(float c[4],
                                         unsigned a0, unsigned a1,
                                         unsigned a2, unsigned a3,
                                         unsigned b0, unsigned b1) {
  asm volatile(
      "mma.sync.aligned.m16n8k8.row.col.f32.tf32.tf32.f32 "
      "{%0,%1,%2,%3}, {%4,%5,%6,%7}, {%8,%9}, {%0,%1,%2,%3};"
      : "+f"(c[0]), "+f"(c[1]), "+f"(c[2]), "+f"(c[3])
      : "r"(a0), "r"(a1), "r"(a2), "r"(a3), "r"(b0), "r"(b1));
}

__global__ __launch_bounds__(256) void gemm_tc_kernel(
    const float* __restrict__ A, const float* __restrict__ W,
    unsigned* __restrict__ C,              // bf16x2 packed, M/2 words per row
    const float* __restrict__ avs, const float* __restrict__ avd,
    float* __restrict__ als, float* __restrict__ ald,
    int N, int K, int M) {
  __shared__ unsigned As[32][132];   // [k][m]  (tf32 bits)
  __shared__ unsigned Bs[32][132];   // [k][n]  (tf32 bits)
  const int bm = blockIdx.y * 128;
  const int bn = blockIdx.x * 128;
  const int tid = threadIdx.x;
  const int warp = tid >> 5, lane = tid & 31;
  const int wm = (warp >> 2) * 64;   // warp M offset: 0 or 64
  const int wn = (warp & 3) * 32;    // warp N offset: 0/32/64/96
  const int lr = lane >> 2;          // 0..7
  const int lc = lane & 3;           // 0..3

  const int arow = tid >> 1;         // 0..127  (A-tile row this thread loads)
  const int acb  = (tid & 1) * 4;    // A float4-chunk base: 0 or 4
  const int brow = tid >> 3;         // 0..31   (B-tile k-row)
  const int bc4  = tid & 7;          // B float4-col base

  const bool rok = (bm + arow) < N;
  const float* Arow = A + (size_t)(bm + arow) * K;

  float acc[4][4][4];
#pragma unroll
  for (int i = 0; i < 4; ++i)
#pragma unroll
    for (int j = 0; j < 4; ++j)
#pragma unroll
      for (int q = 0; q < 4; ++q) acc[i][j][q] = 0.f;

  // prologue: load k0=0 tile into registers
  float4 ra[4], rb[4];
#pragma unroll
  for (int c = 0; c < 4; ++c)
    ra[c] = rok ? *(const float4*)(Arow + (acb + c) * 4)
                : make_float4(0.f, 0.f, 0.f, 0.f);
  {
    const float* Wrow = W + (size_t)brow * M + bn;
#pragma unroll
    for (int j = 0; j < 4; ++j)
      rb[j] = *(const float4*)(Wrow + bc4 * 4 + j * 32);
  }

  for (int k0 = 0; k0 < K; k0 += 32) {
    // commit staged registers to smem (tf32 conversion here, not in MMA loop)
#pragma unroll
    for (int c = 0; c < 4; ++c) {
      int kk = (acb + c) * 4;
      As[kk + 0][arow] = f2tf(ra[c].x);
      As[kk + 1][arow] = f2tf(ra[c].y);
      As[kk + 2][arow] = f2tf(ra[c].z);
      As[kk + 3][arow] = f2tf(ra[c].w);
    }
#pragma unroll
    for (int j = 0; j < 4; ++j)
      *(uint4*)&Bs[brow][bc4 * 4 + j * 32] =
          make_uint4(f2tf(rb[j].x), f2tf(rb[j].y), f2tf(rb[j].z), f2tf(rb[j].w));
    __syncthreads();

    // prefetch next tile (overlaps with mma below)
    if (k0 + 32 < K) {
#pragma unroll
      for (int c = 0; c < 4; ++c)
        ra[c] = rok ? *(const float4*)(Arow + k0 + 32 + (acb + c) * 4)
                    : make_float4(0.f, 0.f, 0.f, 0.f);
      const float* Wrow = W + (size_t)(k0 + 32 + brow) * M + bn;
#pragma unroll
      for (int j = 0; j < 4; ++j)
        rb[j] = *(const float4*)(Wrow + bc4 * 4 + j * 32);
    }

#pragma unroll
    for (int ks = 0; ks < 4; ++ks) {
      const int kb = ks * 8;
      unsigned af[4][4], bf[4][2];
#pragma unroll
      for (int i = 0; i < 4; ++i) {
        int m = wm + i * 16 + lr;
        af[i][0] = As[kb + lc][m];
        af[i][1] = As[kb + lc][m + 8];
        af[i][2] = As[kb + lc + 4][m];
        af[i][3] = As[kb + lc + 4][m + 8];
      }
#pragma unroll
      for (int j = 0; j < 4; ++j) {
        int n = wn + j * 8 + lr;
        bf[j][0] = Bs[kb + lc][n];
        bf[j][1] = Bs[kb + lc + 4][n];
      }
#pragma unroll
      for (int i = 0; i < 4; ++i)
#pragma unroll
        for (int j = 0; j < 4; ++j)
          mma_tf32(acc[i][j], af[i][0], af[i][1], af[i][2], af[i][3],
                   bf[j][0], bf[j][1]);
    }
    __syncthreads();
  }

  // ---- epilogue: bf16x2 stores + fused a_src/a_dst dot partials (fp32) ----
  float avsv[4][2], avdv[4][2];
#pragma unroll
  for (int j = 0; j < 4; ++j) {
    int cb = bn + wn + j * 8 + lc * 2;
    avsv[j][0] = avs[cb]; avsv[j][1] = avs[cb + 1];
    avdv[j][0] = avd[cb]; avdv[j][1] = avd[cb + 1];
  }

  const int Mw = M >> 1;  // words per row
#pragma unroll
  for (int i = 0; i < 4; ++i) {
    int r0 = bm + wm + i * 16 + lr;
    float s0 = 0.f, d0 = 0.f, s1 = 0.f, d1 = 0.f;
#pragma unroll
    for (int j = 0; j < 4; ++j) {
      int cb = bn + wn + j * 8 + lc * 2;
      if (r0 < N)
        C[(size_t)r0 * Mw + (cb >> 1)] = pack_bf16(acc[i][j][0], acc[i][j][1]);
      if (r0 + 8 < N)
        C[(size_t)(r0 + 8) * Mw + (cb >> 1)] =
            pack_bf16(acc[i][j][2], acc[i][j][3]);
      s0 = fmaf(avsv[j][0], acc[i][j][0], fmaf(avsv[j][1], acc[i][j][1], s0));
      d0 = fmaf(avdv[j][0], acc[i][j][0], fmaf(avdv[j][1], acc[i][j][1], d0));
      s1 = fmaf(avsv[j][0], acc[i][j][2], fmaf(avsv[j][1], acc[i][j][3], s1));
      d1 = fmaf(avdv[j][0], acc[i][j][2], fmaf(avdv[j][1], acc[i][j][3], d1));
    }
    // reduce across the 4 lanes (lc = 0..3) sharing each row
#pragma unroll
    for (int o = 1; o < 4; o <<= 1) {
      s0 += __shfl_xor_sync(0xffffffffu, s0, o);
      d0 += __shfl_xor_sync(0xffffffffu, d0, o);
      s1 += __shfl_xor_sync(0xffffffffu, s1, o);
      d1 += __shfl_xor_sync(0xffffffffu, d1, o);
    }
    if (lc == 0) {
      if (r0 < N)     { atomicAdd(&als[r0], s0);     atomicAdd(&ald[r0], d0); }
      if (r0 + 8 < N) { atomicAdd(&als[r0 + 8], s1); atomicAdd(&ald[r0 + 8], d1); }
    }
  }
}

// bf16 bit-exact unpack (bf16 is truncated fp32): 2 ALU ops per pair
__device__ __forceinline__ float blo(unsigned u) { return __uint_as_float(u << 16); }
__device__ __forceinline__ float bhi(unsigned u) { return __uint_as_float(u & 0xffff0000u); }

// ---------------- softmax attention + aggregation (one warp per dst node) ----
// h is packed bf16x2. Register-resident e/exp for deg <= 64; global-scratch
// fallback for larger degrees (impossible for this dataset: Poisson(10)+1).
// Gather loop unrolled x4 for memory-level parallelism.
template <int M, bool RELU>
__global__ __launch_bounds__(256) void attn_agg_kernel(
    const unsigned* __restrict__ h, const float* __restrict__ bias,
    float* __restrict__ out,
    const float* __restrict__ als, const float* __restrict__ ald, int N) {
  int node = (blockIdx.x * blockDim.x + threadIdx.x) >> 5;
  int lane = threadIdx.x & 31;
  if (node >= N) return;
  int beg = g_rowptr[node];
  int end = g_rowptr[node + 1];
  int deg = end - beg;
  float aldn = ald[node];

  constexpr int Mw = M >> 1;        // words per row
  constexpr int NW = Mw / 32;       // words per lane: 4 (M=256) or 2 (M=128)
  float acc[NW * 2];
#pragma unroll
  for (int q = 0; q < NW * 2; ++q) acc[q] = 0.f;

  if (deg <= 64) {
    // ---- fused register path ----
    int s0 = 0, s1 = 0;
    float e0 = -1e30f, e1 = -1e30f;
    if (lane < deg) {
      s0 = g_srcs[beg + lane];
      float e = als[s0] + aldn;
      e0 = (e > 0.f) ? e : 0.2f * e;
    }
    if (32 + lane < deg) {
      s1 = g_srcs[beg + 32 + lane];
      float e = als[s1] + aldn;
      e1 = (e > 0.f) ? e : 0.2f * e;
    }
    float mx = fmaxf(e0, e1);
#pragma unroll
    for (int o = 16; o; o >>= 1)
      mx = fmaxf(mx, __shfl_xor_sync(0xffffffffu, mx, o));
    float ex0 = (lane < deg) ? __expf(e0 - mx) : 0.f;
    float ex1 = (32 + lane < deg) ? __expf(e1 - mx) : 0.f;
    float sum = ex0 + ex1;
#pragma unroll
    for (int o = 16; o; o >>= 1)
      sum += __shfl_xor_sync(0xffffffffu, sum, o);
    float inv = 1.f / sum;

    int jj = 0;
    // unroll-4 main gather loop: 4 independent row loads in flight
    for (; jj + 4 <= deg; jj += 4) {
      int ls[4];
      float al[4];
#pragma unroll
      for (int u = 0; u < 4; ++u) {
        int idx = jj + u;
        ls[u] = __shfl_sync(0xffffffffu, (idx < 32) ? s0 : s1, idx & 31);
        al[u] = __shfl_sync(0xffffffffu, (idx < 32) ? ex0 : ex1, idx & 31) * inv;
      }
      unsigned w[4][NW];
#pragma unroll
      for (int u = 0; u < 4; ++u) {
        if (NW == 4) {
          uint4 v = __ldg((const uint4*)(h + (size_t)ls[u] * Mw) + lane);
          w[u][0] = v.x; w[u][1] = v.y; w[u][2] = v.z; w[u][3] = v.w;
        } else {
          uint2 v = __ldg((const uint2*)(h + (size_t)ls[u] * Mw) + lane);
          w[u][0] = v.x; w[u][1] = v.y;
        }
      }
#pragma unroll
      for (int q = 0; q < NW; ++q) {
#pragma unroll
        for (int u = 0; u < 4; ++u) {
          acc[2 * q + 0] = fmaf(al[u], blo(w[u][q]), acc[2 * q + 0]);
          acc[2 * q + 1] = fmaf(al[u], bhi(w[u][q]), acc[2 * q + 1]);
        }
      }
    }
    // remainder (0..3)
    for (; jj < deg; ++jj) {
      int   ls0 = __shfl_sync(0xffffffffu, (jj < 32) ? s0 : s1, jj & 31);
      float al0 = __shfl_sync(0xffffffffu, (jj < 32) ? ex0 : ex1, jj & 31) * inv;
      unsigned w0[NW];
      if (NW == 4) {
        uint4 v = __ldg((const uint4*)(h + (size_t)ls0 * Mw) + lane);
        w0[0] = v.x; w0[1] = v.y; w0[2] = v.z; w0[3] = v.w;
      } else {
        uint2 v = __ldg((const uint2*)(h + (size_t)ls0 * Mw) + lane);
        w0[0] = v.x; w0[1] = v.y;
      }
#pragma unroll
      for (int q = 0; q < NW; ++q) {
        acc[2 * q + 0] = fmaf(al0, blo(w0[q]), acc[2 * q + 0]);
        acc[2 * q + 1] = fmaf(al0, bhi(w0[q]), acc[2 * q + 1]);
      }
    }
  } else {
    // ---- fallback: global scratch (rare / impossible for this dataset) ----
    float mx = -1e30f;
    for (int j = beg + lane; j < end; j += 32) {
      float e = als[g_srcs[j]] + aldn;
      e = (e > 0.f) ? e : 0.2f * e;
      g_escr[j] = e;
      mx = fmaxf(mx, e);
    }
#pragma unroll
    for (int o = 16; o; o >>= 1)
      mx = fmaxf(mx, __shfl_xor_sync(0xffffffffu, mx, o));
    float sum = 0.f;
    for (int j = beg + lane; j < end; j += 32) {
      float ex = __expf(g_escr[j] - mx);
      g_escr[j] = ex;
      sum += ex;
    }
#pragma unroll
    for (int o = 16; o; o >>= 1)
      sum += __shfl_xor_sync(0xffffffffu, sum, o);
    float inv = 1.f / sum;
    __syncwarp();
    for (int j = beg; j < end; ++j) {
      float al = g_escr[j] * inv;
      unsigned w0[NW];
      if (NW == 4) {
        uint4 v = __ldg((const uint4*)(h + (size_t)g_srcs[j] * Mw) + lane);
        w0[0] = v.x; w0[1] = v.y; w0[2] = v.z; w0[3] = v.w;
      } else {
        uint2 v = __ldg((const uint2*)(h + (size_t)g_srcs[j] * Mw) + lane);
        w0[0] = v.x; w0[1] = v.y;
      }
#pragma unroll
      for (int q = 0; q < NW; ++q) {
        acc[2 * q + 0] = fmaf(al, blo(w0[q]), acc[2 * q + 0]);
        acc[2 * q + 1] = fmaf(al, bhi(w0[q]), acc[2 * q + 1]);
      }
    }
  }

  // lane covers columns [lane*2*NW, lane*2*NW + 2*NW)
  float* orow = out + (size_t)node * M + lane * 2 * NW;
  const float* brow = bias + lane * 2 * NW;
#pragma unroll
  for (int q = 0; q < 2 * NW; q += 4) {
    float4 b = *(const float4*)(brow + q);
    float4 r = make_float4(acc[q] + b.x, acc[q + 1] + b.y,
                           acc[q + 2] + b.z, acc[q + 3] + b.w);
    if (RELU) {
      r.x = fmaxf(r.x, 0.f); r.y = fmaxf(r.y, 0.f);
      r.z = fmaxf(r.z, 0.f); r.w = fmaxf(r.w, 0.f);
    }
    *(float4*)(orow + q) = r;
  }
}

// ---------------- host driver ----------------
extern "C" void kernel_launch(void* const* d_in, const int* in_sizes, int n_in,
                              void* d_out, int out_size) {
  const float* x = (const float*)d_in[0];
  const void* eidx = d_in[1];
  const int base = n_in - 12;
  const float* W1  = (const float*)d_in[base + 0];
  const float* as1 = (const float*)d_in[base + 1];
  const float* ad1 = (const float*)d_in[base + 2];
  const float* b1  = (const float*)d_in[base + 3];
  const float* W2  = (const float*)d_in[base + 4];
  const float* as2 = (const float*)d_in[base + 5];
  const float* ad2 = (const float*)d_in[base + 6];
  const float* b2  = (const float*)d_in[base + 7];
  const float* W3  = (const float*)d_in[base + 8];
  const float* as3 = (const float*)d_in[base + 9];
  const float* ad3 = (const float*)d_in[base + 10];
  const float* b3  = (const float*)d_in[base + 11];

  const int N = in_sizes[0] / 128;
  const int E = in_sizes[1] / 2;

  unsigned* bufA;
  float* bufB;
  float *alsA, *aldA, *alsB, *aldB, *alsC, *aldC;
  cudaGetSymbolAddress((void**)&bufA, g_bufA);
  cudaGetSymbolAddress((void**)&bufB, g_bufB);
  cudaGetSymbolAddress((void**)&alsA, g_alsA);
  cudaGetSymbolAddress((void**)&aldA, g_aldA);
  cudaGetSymbolAddress((void**)&alsB, g_alsB);
  cudaGetSymbolAddress((void**)&aldB, g_aldB);
  cudaGetSymbolAddress((void**)&alsC, g_alsC);
  cudaGetSymbolAddress((void**)&aldC, g_aldC);

  // CSR build (once — shared by all 3 layers) + zero dot accumulators
  init_kernel<<<160, 256>>>(eidx);
  const int quads = (E + 3) / 4;
  hist_kernel<<<(quads + 255) / 256, 256>>>(eidx, E);
  scan_kernel<<<1, 1024>>>(N);
  scatter_kernel<<<(quads + N + 255) / 256, 256>>>(eidx, E, N);

  const int gy = (N + 127) / 128;
  const int agg_blocks = (N + 7) / 8;

  // Layer 1: x[N,128] -> h1(bf16)[N,256] (relu after agg)
  gemm_tc_kernel<<<dim3(2, gy), 256>>>(x, W1, bufA, as1, ad1, alsA, aldA, N, 128, 256);
  attn_agg_kernel<256, true><<<agg_blocks, 256>>>(bufA, b1, bufB, alsA, aldA, N);

  // Layer 2: h1agg[N,256] -> h2(bf16)[N,256]
  gemm_tc_kernel<<<dim3(2, gy), 256>>>(bufB, W2, bufA, as2, ad2, alsB, aldB, N, 256, 256);
  attn_agg_kernel<256, true><<<agg_blocks, 256>>>(bufA, b2, bufB, alsB, aldB, N);

  // Layer 3: h2agg[N,256] -> h3(bf16)[N,128] -> out fp32
  gemm_tc_kernel<<<dim3(1, gy), 256>>>(bufB, W3, bufA, as3, ad3, alsC, aldC, N, 256, 128);
  attn_agg_kernel<128, false><<<agg_blocks, 256>>>(bufA, b3, (float*)d_out, alsC, aldC, N);
}